// round 1
// baseline (speedup 1.0000x reference)
#include <cuda_runtime.h>

#define Dd 1024
#define Bb 16
#define Tt 1024
#define NBLK 128
#define MAXR 0.999f
#define EPSF 1e-8f

// ---------------- device scratch (no allocation allowed) ----------------
__device__ float g_WhEff[Dd * Dd];                 // 4 MB
__device__ float g_pre[(size_t)Tt * Bb * Dd];      // 64 MB: x @ Wx^T + bias
__device__ float g_sigma;
__device__ volatile unsigned g_flags[NBLK];        // grid barrier slots

// ---------------- barrier init (device globals persist across replays) ----------------
__global__ void init_flags_kernel() {
    if (threadIdx.x < NBLK) g_flags[threadIdx.x] = 0u;
}

// ---------------- block-wide sum (1024 threads) ----------------
__device__ __forceinline__ float blk_sum(float v, float* red) {
    int lane = threadIdx.x & 31, warp = threadIdx.x >> 5;
#pragma unroll
    for (int off = 16; off > 0; off >>= 1) v += __shfl_xor_sync(0xffffffffu, v, off);
    if (lane == 0) red[warp] = v;
    __syncthreads();
    if (warp == 0) {
        float x = red[lane];
#pragma unroll
        for (int off = 16; off > 0; off >>= 1) x += __shfl_xor_sync(0xffffffffu, x, off);
        if (lane == 0) red[0] = x;
    }
    __syncthreads();
    float r = red[0];
    __syncthreads();
    return r;
}

// ---------------- 3-step power iteration -> g_sigma ----------------
__global__ void __launch_bounds__(1024) power_iter_kernel(
        const float* __restrict__ Wh, const float* __restrict__ u0) {
    __shared__ float su[Dd];
    __shared__ float sv[Dd];
    __shared__ float red[32];
    const int tid = threadIdx.x;
    su[tid] = u0[tid];
    __syncthreads();

    float normsq_last = 0.f, nu_last = 0.f;
    for (int it = 0; it < 3; it++) {
        // v = Wh^T u  (coalesced column access)
        float acc = 0.f;
        for (int i = 0; i < Dd; i++) acc += Wh[(size_t)i * Dd + tid] * su[i];
        float nv = sqrtf(blk_sum(acc * acc, red)) + EPSF;
        sv[tid] = acc / nv;
        __syncthreads();
        // u = Wh v  (row access, L1-resident)
        float acc2 = 0.f;
        const float* row = Wh + (size_t)tid * Dd;
        for (int j = 0; j < Dd; j++) acc2 += row[j] * sv[j];
        float nsq = blk_sum(acc2 * acc2, red);
        float nu = sqrtf(nsq);
        su[tid] = acc2 / (nu + EPSF);
        __syncthreads();
        if (it == 2) { normsq_last = nsq; nu_last = nu; }
    }
    // sigma = |u . (Wh v)| = ||Wh v||^2 / (||Wh v|| + eps)
    if (tid == 0) g_sigma = fabsf(normsq_last / (nu_last + EPSF));
}

// ---------------- W_h_eff = W_h * radii[i] / (sigma + eps) ----------------
__global__ void __launch_bounds__(256) scale_wh_kernel(
        const float* __restrict__ Wh, const float* __restrict__ log_radii) {
    const int i = blockIdx.x;
    const float r = (1.f / (1.f + expf(-log_radii[i]))) * MAXR;
    const float scale = r / (g_sigma + EPSF);
    const float4* src = (const float4*)(Wh + (size_t)i * Dd);
    float4* dst = (float4*)(g_WhEff + (size_t)i * Dd);
    int j = threadIdx.x;  // 256 threads, 256 float4 per row
    float4 v = src[j];
    v.x *= scale; v.y *= scale; v.z *= scale; v.w *= scale;
    dst[j] = v;
}

// ---------------- SGEMM: g_pre[m][n] = sum_k x[m][k] * Wx[n][k] + b[n] ----------------
// M = 16384, N = 1024, K = 1024. 128x128x16 tile, 256 threads, 8x8 microtile.
__global__ void __launch_bounds__(256) gemm_kernel(
        const float* __restrict__ A, const float* __restrict__ W,
        const float* __restrict__ bias) {
    __shared__ float As[16][132];
    __shared__ float Bs[16][132];
    const int tid = threadIdx.x;
    const int tx = tid & 15, ty = tid >> 4;
    const int m0 = blockIdx.y * 128, n0 = blockIdx.x * 128;
    const int lrow = tid >> 2, lcol = (tid & 3) << 2;

    const float* Aptr = A + (size_t)(m0 + lrow) * Dd + lcol;
    const float* Wptr = W + (size_t)(n0 + lrow) * Dd + lcol;

    float4 a0 = *(const float4*)(Aptr);
    float4 a1 = *(const float4*)(Aptr + (size_t)64 * Dd);
    float4 b0 = *(const float4*)(Wptr);
    float4 b1 = *(const float4*)(Wptr + (size_t)64 * Dd);

    float acc[8][8];
#pragma unroll
    for (int i = 0; i < 8; i++)
#pragma unroll
        for (int j = 0; j < 8; j++) acc[i][j] = 0.f;

    for (int k0 = 0; k0 < Dd; k0 += 16) {
        __syncthreads();  // previous compute done
        As[lcol + 0][lrow] = a0.x; As[lcol + 1][lrow] = a0.y;
        As[lcol + 2][lrow] = a0.z; As[lcol + 3][lrow] = a0.w;
        As[lcol + 0][lrow + 64] = a1.x; As[lcol + 1][lrow + 64] = a1.y;
        As[lcol + 2][lrow + 64] = a1.z; As[lcol + 3][lrow + 64] = a1.w;
        Bs[lcol + 0][lrow] = b0.x; Bs[lcol + 1][lrow] = b0.y;
        Bs[lcol + 2][lrow] = b0.z; Bs[lcol + 3][lrow] = b0.w;
        Bs[lcol + 0][lrow + 64] = b1.x; Bs[lcol + 1][lrow + 64] = b1.y;
        Bs[lcol + 2][lrow + 64] = b1.z; Bs[lcol + 3][lrow + 64] = b1.w;
        __syncthreads();

        if (k0 + 16 < Dd) {  // register prefetch of next tile
            a0 = *(const float4*)(Aptr + k0 + 16);
            a1 = *(const float4*)(Aptr + (size_t)64 * Dd + k0 + 16);
            b0 = *(const float4*)(Wptr + k0 + 16);
            b1 = *(const float4*)(Wptr + (size_t)64 * Dd + k0 + 16);
        }

#pragma unroll
        for (int k = 0; k < 16; k++) {
            float ar[8], br[8];
            *(float4*)(ar) = *(const float4*)&As[k][ty * 8];
            *(float4*)(ar + 4) = *(const float4*)&As[k][ty * 8 + 4];
            *(float4*)(br) = *(const float4*)&Bs[k][tx * 8];
            *(float4*)(br + 4) = *(const float4*)&Bs[k][tx * 8 + 4];
#pragma unroll
            for (int i = 0; i < 8; i++)
#pragma unroll
                for (int j = 0; j < 8; j++) acc[i][j] += ar[i] * br[j];
        }
    }

    float bj[8];
#pragma unroll
    for (int j = 0; j < 8; j++) bj[j] = bias[n0 + tx * 8 + j];
#pragma unroll
    for (int i = 0; i < 8; i++) {
        float* Crow = g_pre + (size_t)(m0 + ty * 8 + i) * Dd + n0 + tx * 8;
        float4 v0, v1;
        v0.x = acc[i][0] + bj[0]; v0.y = acc[i][1] + bj[1];
        v0.z = acc[i][2] + bj[2]; v0.w = acc[i][3] + bj[3];
        v1.x = acc[i][4] + bj[4]; v1.y = acc[i][5] + bj[5];
        v1.z = acc[i][6] + bj[6]; v1.w = acc[i][7] + bj[7];
        *(float4*)(Crow) = v0;
        *(float4*)(Crow + 4) = v1;
    }
}

// ---------------- flags-array grid barrier ----------------
__device__ __forceinline__ void gbar(unsigned target, int tid, int bid) {
    __threadfence();
    __syncthreads();
    if (tid == 0) g_flags[bid] = target;
    if (tid < NBLK) {
        while (g_flags[tid] < target) { }
    }
    __threadfence();
    __syncthreads();
}

// ---------------- persistent recurrence ----------------
// 128 blocks x 256 threads; block owns 8 output dims. W slice stays in SMEM for
// all 1024 steps; h_prev (64KB) staged per step. Warp = (dim-quad, batch-quad)
// tile, lane = 32-way k split, butterfly reduce.
__global__ void __launch_bounds__(256) recurrent_kernel(
        const float* __restrict__ z, const float* __restrict__ h0,
        float* __restrict__ outs, float* __restrict__ hall) {
    extern __shared__ float smem[];
    float* sW = smem;            // [8][1024] = 32 KB
    float* sh = smem + 8 * Dd;   // [16][1024] = 64 KB

    const int tid = threadIdx.x, bid = blockIdx.x;
    const int dbase = bid * 8;

    // preload my W_h_eff rows (persist across all steps)
    {
        const float4* wsrc = (const float4*)(g_WhEff + (size_t)dbase * Dd);
        for (int i = tid; i < 8 * Dd / 4; i += 256) ((float4*)sW)[i] = wsrc[i];
    }
    // write h_all[0] = h0 (my dims only; union over blocks covers all)
    if (tid < 128) {
        int b = tid >> 3, d = dbase + (tid & 7);
        hall[b * Dd + d] = h0[b * Dd + d];
    }
    gbar(1u, tid, bid);

    const int warp = tid >> 5, lane = tid & 31;
    const int dg = warp & 1, bg = warp >> 1;
    const float* w0p = sW + (dg * 4 + 0) * Dd;
    const float* w1p = sW + (dg * 4 + 1) * Dd;
    const float* w2p = sW + (dg * 4 + 2) * Dd;
    const float* w3p = sW + (dg * 4 + 3) * Dd;
    const float* ha_p = sh + (bg * 4 + 0) * Dd;
    const float* hb_p = sh + (bg * 4 + 1) * Dd;
    const float* hc_p = sh + (bg * 4 + 2) * Dd;
    const float* hd_p = sh + (bg * 4 + 3) * Dd;

    for (int t = 0; t < Tt; t++) {
        // stage h_prev = h_all[t]
        {
            const float4* hsrc = (const float4*)(hall + (size_t)t * Bb * Dd);
            for (int i = tid; i < Bb * Dd / 4; i += 256) ((float4*)sh)[i] = hsrc[i];
        }
        __syncthreads();

        float acc[16];
#pragma unroll
        for (int j = 0; j < 16; j++) acc[j] = 0.f;

#pragma unroll 4
        for (int i = 0; i < 32; i++) {
            const int k = i * 32 + lane;
            const float w0 = w0p[k], w1 = w1p[k], w2 = w2p[k], w3 = w3p[k];
            const float ha = ha_p[k], hb = hb_p[k], hc = hc_p[k], hd = hd_p[k];
            acc[0]  += w0 * ha; acc[1]  += w0 * hb; acc[2]  += w0 * hc; acc[3]  += w0 * hd;
            acc[4]  += w1 * ha; acc[5]  += w1 * hb; acc[6]  += w1 * hc; acc[7]  += w1 * hd;
            acc[8]  += w2 * ha; acc[9]  += w2 * hb; acc[10] += w2 * hc; acc[11] += w2 * hd;
            acc[12] += w3 * ha; acc[13] += w3 * hb; acc[14] += w3 * hc; acc[15] += w3 * hd;
        }
#pragma unroll
        for (int off = 16; off > 0; off >>= 1) {
#pragma unroll
            for (int j = 0; j < 16; j++)
                acc[j] += __shfl_xor_sync(0xffffffffu, acc[j], off);
        }

        if (lane == 0) {
            const size_t baseT = (size_t)t * Bb * Dd;
            const int d0 = dbase + dg * 4;
#pragma unroll
            for (int c = 0; c < 4; c++) {
                const int b = bg * 4 + c;
                const size_t off = baseT + (size_t)b * Dd + d0;
                const float4 p = *(const float4*)(g_pre + off);
                float4 hn;
                hn.x = tanhf(p.x + acc[0 * 4 + c]);
                hn.y = tanhf(p.y + acc[1 * 4 + c]);
                hn.z = tanhf(p.z + acc[2 * 4 + c]);
                hn.w = tanhf(p.w + acc[3 * 4 + c]);
                *(float4*)(hall + off + Bb * Dd) = hn;  // h_all[t+1]
                const float4 zf = *(const float4*)(z + off);
                float4 o;
                o.x = hn.x * (zf.x / (1.f + expf(-zf.x)));
                o.y = hn.y * (zf.y / (1.f + expf(-zf.y)));
                o.z = hn.z * (zf.z / (1.f + expf(-zf.z)));
                o.w = hn.w * (zf.w / (1.f + expf(-zf.w)));
                *(float4*)(outs + off) = o;
            }
        }
        if (t + 1 < Tt) gbar((unsigned)(t + 2), tid, bid);
    }
}

// ---------------- launch ----------------
extern "C" void kernel_launch(void* const* d_in, const int* in_sizes, int n_in,
                              void* d_out, int out_size) {
    const float* x   = (const float*)d_in[0];  // [T,B,D]
    const float* z   = (const float*)d_in[1];  // [T,B,D]
    const float* h0  = (const float*)d_in[2];  // [B,D]
    const float* Wx  = (const float*)d_in[3];  // [D,D]
    const float* Wh  = (const float*)d_in[4];  // [D,D]
    const float* lr  = (const float*)d_in[5];  // [D]
    const float* bia = (const float*)d_in[6];  // [D]
    const float* u0  = (const float*)d_in[7];  // [D]

    float* outs = (float*)d_out;                         // [T,B,D]
    float* hall = (float*)d_out + (size_t)Tt * Bb * Dd;  // [T+1,B,D]

    const size_t rec_smem = (size_t)(8 + 16) * Dd * sizeof(float);  // 96 KB
    cudaFuncSetAttribute(recurrent_kernel,
                         cudaFuncAttributeMaxDynamicSharedMemorySize,
                         (int)rec_smem);

    init_flags_kernel<<<1, NBLK>>>();
    power_iter_kernel<<<1, 1024>>>(Wh, u0);
    scale_wh_kernel<<<Dd, 256>>>(Wh, lr);
    {
        dim3 grid(Dd / 128, (Tt * Bb) / 128);  // (8, 128)
        gemm_kernel<<<grid, 256>>>(x, Wx, bia);
    }
    recurrent_kernel<<<NBLK, 256, rec_smem>>>(z, h0, outs, hall);
}

// round 2
// speedup vs baseline: 2.7842x; 2.7842x over previous
#include <cuda_runtime.h>
#include <cstdint>

#define Dd 1024
#define Bb 16
#define Tt 1024
#define NBLK 128
#define MAXR 0.999f
#define EPSF 1e-8f

// ---------------- device scratch (no allocation allowed) ----------------
__device__ float g_WhEff[Dd * Dd];                 // 4 MB
__device__ float g_pre[(size_t)Tt * Bb * Dd];      // 64 MB: x @ Wx^T + bias
__device__ float g_sigma;
__device__ unsigned g_arrive;
__device__ volatile unsigned g_release;

// ---------------- f32x2 helpers (sm_103a packed fp32) ----------------
__device__ __forceinline__ unsigned long long pk2(float lo, float hi) {
    unsigned long long r;
    asm("mov.b64 %0, {%1, %2};" : "=l"(r) : "f"(lo), "f"(hi));
    return r;
}
__device__ __forceinline__ float2 up2(unsigned long long v) {
    float2 r;
    asm("mov.b64 {%0, %1}, %2;" : "=f"(r.x), "=f"(r.y) : "l"(v));
    return r;
}
__device__ __forceinline__ void fma2(unsigned long long& d, unsigned long long a,
                                     unsigned long long b) {
    asm("fma.rn.f32x2 %0, %1, %2, %0;" : "+l"(d) : "l"(a), "l"(b));
}
__device__ __forceinline__ unsigned long long add2(unsigned long long a,
                                                   unsigned long long b) {
    unsigned long long r;
    asm("add.rn.f32x2 %0, %1, %2;" : "=l"(r) : "l"(a), "l"(b));
    return r;
}
__device__ __forceinline__ uint32_t s2u(const void* p) {
    uint32_t a;
    asm("{ .reg .u64 t; cvta.to.shared.u64 t, %1; cvt.u32.u64 %0, t; }"
        : "=r"(a) : "l"(p));
    return a;
}

// ---------------- per-launch init (device globals persist across replays) ---
__global__ void init_kernel() {
    g_arrive = 0u;
    g_release = 0u;
}

// ---------------- block-wide sum (1024 threads) ----------------
__device__ __forceinline__ float blk_sum(float v, float* red) {
    int lane = threadIdx.x & 31, warp = threadIdx.x >> 5;
#pragma unroll
    for (int off = 16; off > 0; off >>= 1) v += __shfl_xor_sync(0xffffffffu, v, off);
    if (lane == 0) red[warp] = v;
    __syncthreads();
    if (warp == 0) {
        float x = red[lane];
#pragma unroll
        for (int off = 16; off > 0; off >>= 1) x += __shfl_xor_sync(0xffffffffu, x, off);
        if (lane == 0) red[0] = x;
    }
    __syncthreads();
    float r = red[0];
    __syncthreads();
    return r;
}

// ---------------- 3-step power iteration -> g_sigma ----------------
__global__ void __launch_bounds__(1024) power_iter_kernel(
        const float* __restrict__ Wh, const float* __restrict__ u0) {
    __shared__ float su[Dd];
    __shared__ float sv[Dd];
    __shared__ float red[32];
    const int tid = threadIdx.x;
    su[tid] = u0[tid];
    __syncthreads();

    float normsq_last = 0.f, nu_last = 0.f;
    for (int it = 0; it < 3; it++) {
        float acc = 0.f;
        for (int i = 0; i < Dd; i++) acc += Wh[(size_t)i * Dd + tid] * su[i];
        float nv = sqrtf(blk_sum(acc * acc, red)) + EPSF;
        sv[tid] = acc / nv;
        __syncthreads();
        float acc2 = 0.f;
        const float* row = Wh + (size_t)tid * Dd;
        for (int j = 0; j < Dd; j++) acc2 += row[j] * sv[j];
        float nsq = blk_sum(acc2 * acc2, red);
        float nu = sqrtf(nsq);
        su[tid] = acc2 / (nu + EPSF);
        __syncthreads();
        if (it == 2) { normsq_last = nsq; nu_last = nu; }
    }
    if (tid == 0) g_sigma = fabsf(normsq_last / (nu_last + EPSF));
}

// ---------------- W_h_eff = W_h * radii[i] / (sigma + eps) ----------------
__global__ void __launch_bounds__(256) scale_wh_kernel(
        const float* __restrict__ Wh, const float* __restrict__ log_radii) {
    const int i = blockIdx.x;
    const float r = (1.f / (1.f + expf(-log_radii[i]))) * MAXR;
    const float scale = r / (g_sigma + EPSF);
    const float4* src = (const float4*)(Wh + (size_t)i * Dd);
    float4* dst = (float4*)(g_WhEff + (size_t)i * Dd);
    int j = threadIdx.x;
    float4 v = src[j];
    v.x *= scale; v.y *= scale; v.z *= scale; v.w *= scale;
    dst[j] = v;
}

// ---------------- SGEMM with packed f32x2 FMA ----------------
// g_pre[m][n] = sum_k x[m][k] * Wx[n][k] + b[n]; M=16384, N=1024, K=1024.
__global__ void __launch_bounds__(256) gemm_kernel(
        const float* __restrict__ A, const float* __restrict__ W,
        const float* __restrict__ bias) {
    __shared__ float As[16][132];
    __shared__ float Bs[16][132];
    const int tid = threadIdx.x;
    const int tx = tid & 15, ty = tid >> 4;
    const int m0 = blockIdx.y * 128, n0 = blockIdx.x * 128;
    const int lrow = tid >> 2, lcol = (tid & 3) << 2;

    const float* Aptr = A + (size_t)(m0 + lrow) * Dd + lcol;
    const float* Wptr = W + (size_t)(n0 + lrow) * Dd + lcol;

    float4 a0 = *(const float4*)(Aptr);
    float4 a1 = *(const float4*)(Aptr + (size_t)64 * Dd);
    float4 b0 = *(const float4*)(Wptr);
    float4 b1 = *(const float4*)(Wptr + (size_t)64 * Dd);

    unsigned long long acc2[8][4];
#pragma unroll
    for (int i = 0; i < 8; i++)
#pragma unroll
        for (int j = 0; j < 4; j++) acc2[i][j] = 0ULL;

    for (int k0 = 0; k0 < Dd; k0 += 16) {
        __syncthreads();
        As[lcol + 0][lrow] = a0.x; As[lcol + 1][lrow] = a0.y;
        As[lcol + 2][lrow] = a0.z; As[lcol + 3][lrow] = a0.w;
        As[lcol + 0][lrow + 64] = a1.x; As[lcol + 1][lrow + 64] = a1.y;
        As[lcol + 2][lrow + 64] = a1.z; As[lcol + 3][lrow + 64] = a1.w;
        Bs[lcol + 0][lrow] = b0.x; Bs[lcol + 1][lrow] = b0.y;
        Bs[lcol + 2][lrow] = b0.z; Bs[lcol + 3][lrow] = b0.w;
        Bs[lcol + 0][lrow + 64] = b1.x; Bs[lcol + 1][lrow + 64] = b1.y;
        Bs[lcol + 2][lrow + 64] = b1.z; Bs[lcol + 3][lrow + 64] = b1.w;
        __syncthreads();

        if (k0 + 16 < Dd) {
            a0 = *(const float4*)(Aptr + k0 + 16);
            a1 = *(const float4*)(Aptr + (size_t)64 * Dd + k0 + 16);
            b0 = *(const float4*)(Wptr + k0 + 16);
            b1 = *(const float4*)(Wptr + (size_t)64 * Dd + k0 + 16);
        }

#pragma unroll
        for (int k = 0; k < 16; k++) {
            float ar[8];
            *(float4*)(ar) = *(const float4*)&As[k][ty * 8];
            *(float4*)(ar + 4) = *(const float4*)&As[k][ty * 8 + 4];
            unsigned long long brp[4];
            const unsigned long long* b64 = (const unsigned long long*)&Bs[k][tx * 8];
            brp[0] = b64[0]; brp[1] = b64[1]; brp[2] = b64[2]; brp[3] = b64[3];
#pragma unroll
            for (int i = 0; i < 8; i++) {
                unsigned long long ad = pk2(ar[i], ar[i]);
#pragma unroll
                for (int j = 0; j < 4; j++) fma2(acc2[i][j], ad, brp[j]);
            }
        }
    }

    float bj[8];
#pragma unroll
    for (int j = 0; j < 8; j++) bj[j] = bias[n0 + tx * 8 + j];
#pragma unroll
    for (int i = 0; i < 8; i++) {
        float* Crow = g_pre + (size_t)(m0 + ty * 8 + i) * Dd + n0 + tx * 8;
        float c[8];
#pragma unroll
        for (int j = 0; j < 4; j++) {
            float2 f = up2(acc2[i][j]);
            c[2 * j] = f.x + bj[2 * j];
            c[2 * j + 1] = f.y + bj[2 * j + 1];
        }
        *(float4*)(Crow) = make_float4(c[0], c[1], c[2], c[3]);
        *(float4*)(Crow + 4) = make_float4(c[4], c[5], c[6], c[7]);
    }
}

// ---------------- persistent recurrence ----------------
// 128 blocks x 256 threads; block owns 8 output dims, all 16 batches.
// W slice (32KB) persistent in SMEM; h_prev staged via cp.async.bulk + mbarrier.
// Warp tile: 8 dims x 4 batches, 2-warp k-split, packed f32x2 over k-pairs.
// Barrier: 1 atomic arrival + 1 release-word poller per block.
__global__ void __launch_bounds__(256, 1) recurrent_kernel(
        const float* __restrict__ z, const float* __restrict__ h0,
        float* __restrict__ outs, float* __restrict__ hall) {
    extern __shared__ float smem[];
    float* sW = smem;                 // [8][1024] = 32 KB
    float* sh = smem + 8 * Dd;        // [16][1024] = 64 KB
    float* red = smem + 24 * Dd;      // [128]
    unsigned long long* mbar = (unsigned long long*)(smem + 24 * Dd + 128);

    const int tid = threadIdx.x, bid = blockIdx.x;
    const int dbase = bid * 8;
    const uint32_t sh_u = s2u(sh);
    const uint32_t mbar_u = s2u(mbar);

    // preload my W_h_eff rows (persist across all steps)
    {
        const float4* wsrc = (const float4*)(g_WhEff + (size_t)dbase * Dd);
        for (int i = tid; i < 8 * Dd / 4; i += 256) ((float4*)sW)[i] = wsrc[i];
    }
    // write h_all[0] stripe (pure output; nobody reads it this launch)
    if (tid < 128) {
        int b = tid >> 3, d = dbase + (tid & 7);
        hall[b * Dd + d] = h0[b * Dd + d];
    }
    if (tid == 0) {
        asm volatile("mbarrier.init.shared.b64 [%0], %1;"
                     :: "r"(mbar_u), "r"(1) : "memory");
    }
    __syncthreads();

    const int warp = tid >> 5, lane = tid & 31;
    const int tb = warp >> 1;   // batch group (4 batches)
    const int kw = warp & 1;    // k-split half
    const unsigned long long* w64 = (const unsigned long long*)sW;
    const unsigned long long* h64 =
        (const unsigned long long*)sh + (size_t)tb * 4 * (Dd / 2);

    // epilogue mapping (tid < 128): one (batch, dim) output per thread
    const int eb = (tid >> 5) * 4 + (tid & 3);
    const int ed = dbase + ((tid & 31) >> 2);

    for (int t = 0; t < Tt; t++) {
        const size_t off_e = (size_t)t * Bb * Dd + (size_t)eb * Dd + ed;
        float pre_v = 0.f, z_v = 0.f;
        if (tid < 128) {       // prefetch DRAM operands off the critical path
            pre_v = g_pre[off_e];
            z_v = z[off_e];
        }

        // stage h_prev into smem via bulk DMA
        if (tid == 0) {
            const float* src = (t == 0) ? h0 : (hall + (size_t)t * Bb * Dd);
            asm volatile("mbarrier.arrive.expect_tx.shared.b64 _, [%0], %1;"
                         :: "r"(mbar_u), "r"(Bb * Dd * 4) : "memory");
            asm volatile(
                "cp.async.bulk.shared::cluster.global.mbarrier::complete_tx::bytes "
                "[%0], [%1], %2, [%3];"
                :: "r"(sh_u), "l"(src), "r"(Bb * Dd * 4), "r"(mbar_u) : "memory");
        }
        {   // all threads wait for DMA completion (parity = t&1)
            const uint32_t phase = (uint32_t)(t & 1);
            uint32_t ready;
            do {
                asm volatile(
                    "{\n\t.reg .pred P;\n\t"
                    "mbarrier.try_wait.parity.acquire.cta.shared::cta.b64 P, [%1], %2, 0x989680;\n\t"
                    "selp.b32 %0, 1, 0, P;\n\t}"
                    : "=r"(ready) : "r"(mbar_u), "r"(phase) : "memory");
            } while (!ready);
        }

        // inner product: 8 dims x 4 batches, k-pairs packed in f32x2
        unsigned long long acc[32];
#pragma unroll
        for (int i = 0; i < 32; i++) acc[i] = 0ULL;
#pragma unroll
        for (int it = 0; it < 8; it++) {
            const int kp = kw * 256 + it * 32 + lane;
            unsigned long long wv[8], hv[4];
#pragma unroll
            for (int d = 0; d < 8; d++) wv[d] = w64[d * (Dd / 2) + kp];
#pragma unroll
            for (int b = 0; b < 4; b++) hv[b] = h64[b * (Dd / 2) + kp];
#pragma unroll
            for (int d = 0; d < 8; d++)
#pragma unroll
                for (int b = 0; b < 4; b++) fma2(acc[d * 4 + b], wv[d], hv[b]);
        }

        // butterfly-fold: 31 shfl.64; lane l ends owning output index l
#pragma unroll
        for (int off = 16; off > 0; off >>= 1) {
#pragma unroll
            for (int j = 0; j < off; j++) {
                unsigned long long send = (lane & off) ? acc[j] : acc[j + off];
                unsigned long long recv = __shfl_xor_sync(0xffffffffu, send, off);
                acc[j] = add2((lane & off) ? acc[j + off] : acc[j], recv);
            }
        }
        float2 f2 = up2(acc[0]);
        const float myv = f2.x + f2.y;

        // cross-k-warp combine through smem
        const int ridx = tb * 32 + lane;
        if (kw == 0) red[ridx] = myv;
        __syncthreads();
        if (kw == 1) red[ridx] += myv;
        __syncthreads();

        // epilogue: 128 threads, one output each
        float hn = 0.f;
        if (tid < 128) {
            hn = tanhf(red[tid] + pre_v);
            hall[off_e + Bb * Dd] = hn;   // h_all[t+1]
        }
        __threadfence();
        __syncthreads();
        if (tid == 0) {
            unsigned old = atomicAdd(&g_arrive, 1u);
            if (old == (unsigned)((t + 1) * NBLK - 1)) g_release = (unsigned)(t + 1);
        }
        // silu gate overlapped with barrier propagation
        if (tid < 128) {
            float sg = z_v / (1.f + expf(-z_v));
            outs[off_e] = hn * sg;
        }
        if (t + 1 < Tt) {
            if (tid == 0) {
                while (g_release < (unsigned)(t + 1)) { }
            }
            __syncthreads();
        }
    }
}

// ---------------- launch ----------------
extern "C" void kernel_launch(void* const* d_in, const int* in_sizes, int n_in,
                              void* d_out, int out_size) {
    const float* x   = (const float*)d_in[0];  // [T,B,D]
    const float* z   = (const float*)d_in[1];  // [T,B,D]
    const float* h0  = (const float*)d_in[2];  // [B,D]
    const float* Wx  = (const float*)d_in[3];  // [D,D]
    const float* Wh  = (const float*)d_in[4];  // [D,D]
    const float* lr  = (const float*)d_in[5];  // [D]
    const float* bia = (const float*)d_in[6];  // [D]
    const float* u0  = (const float*)d_in[7];  // [D]

    float* outs = (float*)d_out;                         // [T,B,D]
    float* hall = (float*)d_out + (size_t)Tt * Bb * Dd;  // [T+1,B,D]

    const size_t rec_smem = (size_t)(24 * Dd + 128) * sizeof(float) + 16;
    cudaFuncSetAttribute(recurrent_kernel,
                         cudaFuncAttributeMaxDynamicSharedMemorySize,
                         (int)rec_smem);

    init_kernel<<<1, 1>>>();
    power_iter_kernel<<<1, 1024>>>(Wh, u0);
    scale_wh_kernel<<<Dd, 256>>>(Wh, lr);
    {
        dim3 grid(Dd / 128, (Tt * Bb) / 128);  // (8, 128)
        gemm_kernel<<<grid, 256>>>(x, Wx, bia);
    }
    recurrent_kernel<<<NBLK, 256, rec_smem>>>(z, h0, outs, hall);
}